// round 1
// baseline (speedup 1.0000x reference)
#include <cuda_runtime.h>
#include <math.h>

// Problem constants
#define BB 8
#define LL 1024
#define DD 1024
#define HH 16
#define DK 64
#define ROWS_TOT (BB*LL)          // 8192

// Scratch (device globals; no allocation allowed)
__device__ float g_qh[(size_t)ROWS_TOT * DD];   // (b,l,h,d) == (row, h*64+d)
__device__ float g_kh[(size_t)ROWS_TOT * DD];
__device__ float g_vh[(size_t)ROWS_TOT * DD];
__device__ float g_ctx[(size_t)ROWS_TOT * DD];  // (b,q,h,d)

// ---------------------------------------------------------------------------
// C[M,N] = (A[M,K] @ W[N,K]^T + bias[N]) * npm[row] * scale
// 128x128 tile, BK=8, 256 threads, 8x8 register microtile.
// ---------------------------------------------------------------------------
__global__ __launch_bounds__(256) void sgemm_bias(
    const float* __restrict__ A, const float* __restrict__ W,
    const float* __restrict__ bias, const float* __restrict__ npm,
    float scale, float* __restrict__ C, int M, int N, int K)
{
    __shared__ float As[8][128];
    __shared__ float Ws[8][128];
    const int tid = threadIdx.x;
    const int bm = blockIdx.y * 128;
    const int bn = blockIdx.x * 128;
    const int tr = tid >> 4;        // 0..15
    const int tc = tid & 15;        // 0..15
    const int lr = tid >> 1;        // 0..127
    const int lk = (tid & 1) * 4;   // 0 or 4

    const float* Ap = A + (size_t)(bm + lr) * K + lk;
    const float* Wp = W + (size_t)(bn + lr) * K + lk;

    float acc[8][8];
#pragma unroll
    for (int i = 0; i < 8; i++)
#pragma unroll
        for (int j = 0; j < 8; j++) acc[i][j] = 0.f;

    for (int kb = 0; kb < K; kb += 8) {
        float4 av = *(const float4*)(Ap + kb);
        float4 wv = *(const float4*)(Wp + kb);
        __syncthreads();
        As[lk + 0][lr] = av.x; As[lk + 1][lr] = av.y;
        As[lk + 2][lr] = av.z; As[lk + 3][lr] = av.w;
        Ws[lk + 0][lr] = wv.x; Ws[lk + 1][lr] = wv.y;
        Ws[lk + 2][lr] = wv.z; Ws[lk + 3][lr] = wv.w;
        __syncthreads();
#pragma unroll
        for (int k = 0; k < 8; k++) {
            float a[8], w[8];
            *(float4*)&a[0] = *(const float4*)&As[k][tr * 8];
            *(float4*)&a[4] = *(const float4*)&As[k][tr * 8 + 4];
            *(float4*)&w[0] = *(const float4*)&Ws[k][tc * 8];
            *(float4*)&w[4] = *(const float4*)&Ws[k][tc * 8 + 4];
#pragma unroll
            for (int i = 0; i < 8; i++)
#pragma unroll
                for (int j = 0; j < 8; j++)
                    acc[i][j] += a[i] * w[j];
        }
    }

    const int colBase = bn + tc * 8;
    float bsv[8];
#pragma unroll
    for (int j = 0; j < 8; j++) bsv[j] = bias[colBase + j];
#pragma unroll
    for (int i = 0; i < 8; i++) {
        int row = bm + tr * 8 + i;
        float nv = npm[row] * scale;
        float4 o0, o1;
        o0.x = (acc[i][0] + bsv[0]) * nv;
        o0.y = (acc[i][1] + bsv[1]) * nv;
        o0.z = (acc[i][2] + bsv[2]) * nv;
        o0.w = (acc[i][3] + bsv[3]) * nv;
        o1.x = (acc[i][4] + bsv[4]) * nv;
        o1.y = (acc[i][5] + bsv[5]) * nv;
        o1.z = (acc[i][6] + bsv[6]) * nv;
        o1.w = (acc[i][7] + bsv[7]) * nv;
        *(float4*)&C[(size_t)row * N + colBase] = o0;
        *(float4*)&C[(size_t)row * N + colBase + 4] = o1;
    }
}

// ---------------------------------------------------------------------------
// Fused attention: per block = (b,h) x 32 q-rows.
// S(32x1024) in smem -> mask -> softmax (attn written to gmem) -> P@V -> ctx
// smem: S 32*1024 | Qs 32*64 | KV 256*68   = 208,896 B
// ---------------------------------------------------------------------------
#define ATT_SMEM ((32*1024 + 32*64 + 256*68) * 4)

__global__ __launch_bounds__(256) void attn_kernel(
    const float* __restrict__ qh, const float* __restrict__ kh,
    const float* __restrict__ vh, const int* __restrict__ mask,
    float* __restrict__ attn, float* __restrict__ ctx)
{
    extern __shared__ float sm[];
    float* S  = sm;                      // [32][1024]
    float* Qs = sm + 32 * 1024;          // [32][64]
    float* KV = Qs + 32 * 64;            // [256][68] (padded)

    const int tid = threadIdx.x;
    const int bh  = blockIdx.x;          // b*16 + h
    const int b   = bh >> 4;
    const int h   = bh & 15;
    const int q0  = blockIdx.y * 32;

    const float* qhp = qh + (size_t)b * LL * DD + h * DK;
    const float* khp = kh + (size_t)b * LL * DD + h * DK;
    const float* vhp = vh + (size_t)b * LL * DD + h * DK;

    // ---- load Q block (32 x 64) ----
    for (int i = tid; i < 32 * 16; i += 256) {
        int r = i >> 4, s = i & 15;
        float4 v = *(const float4*)(qhp + (size_t)(q0 + r) * DD + s * 4);
        *(float4*)&Qs[r * 64 + s * 4] = v;
    }

    // ---- S = Q @ K^T  (scale folded into qh) ----
    const int qi0 = (tid >> 5) * 4;      // 0..28
    const int kjl = tid & 31;            // lane kj base
    for (int kp = 0; kp < 4; kp++) {
        __syncthreads();
        // load K tile: 256 rows x 64 d
        for (int i = tid; i < 256 * 16; i += 256) {
            int r = i >> 4, s = i & 15;
            float4 v = *(const float4*)(khp + (size_t)(kp * 256 + r) * DD + s * 4);
            *(float4*)&KV[r * 68 + s * 4] = v;
        }
        __syncthreads();
        float acc[4][8];
#pragma unroll
        for (int i = 0; i < 4; i++)
#pragma unroll
            for (int j = 0; j < 8; j++) acc[i][j] = 0.f;
#pragma unroll
        for (int d4 = 0; d4 < 16; d4++) {
            float4 qv[4];
#pragma unroll
            for (int i = 0; i < 4; i++)
                qv[i] = *(const float4*)&Qs[(qi0 + i) * 64 + d4 * 4];
#pragma unroll
            for (int j = 0; j < 8; j++) {
                float4 kv = *(const float4*)&KV[(kjl + 32 * j) * 68 + d4 * 4];
#pragma unroll
                for (int i = 0; i < 4; i++)
                    acc[i][j] += qv[i].x * kv.x + qv[i].y * kv.y +
                                 qv[i].z * kv.z + qv[i].w * kv.w;
            }
        }
#pragma unroll
        for (int i = 0; i < 4; i++)
#pragma unroll
            for (int j = 0; j < 8; j++)
                S[(qi0 + i) * 1024 + kp * 256 + kjl + 32 * j] = acc[i][j];
    }
    __syncthreads();

    // ---- mask ----
    {
        const int4* mp4 = (const int4*)(mask + ((size_t)b * LL + q0) * LL);
        for (int i = tid; i < 32 * 256; i += 256) {
            int4 m4 = mp4[i];
            float4* s4 = (float4*)&S[i * 4];
            float4 sv = *s4;
            if (m4.x) sv.x = -1e30f;
            if (m4.y) sv.y = -1e30f;
            if (m4.z) sv.z = -1e30f;
            if (m4.w) sv.w = -1e30f;
            *s4 = sv;
        }
    }
    __syncthreads();

    // ---- softmax per row (warp handles 4 rows) + write attn ----
    {
        const int wid = tid >> 5, lane = tid & 31;
        float* attnBase = attn + ((size_t)bh * LL + q0) * LL;
#pragma unroll
        for (int rr = 0; rr < 4; rr++) {
            int r = wid * 4 + rr;
            float* Sr = S + r * 1024;
            float m = -1e30f;
            for (int c = lane; c < 1024; c += 32) m = fmaxf(m, Sr[c]);
#pragma unroll
            for (int o = 16; o; o >>= 1) m = fmaxf(m, __shfl_xor_sync(0xffffffffu, m, o));
            float sum = 0.f;
            for (int c = lane; c < 1024; c += 32) {
                float s = Sr[c];
                float e = (s <= -9e29f) ? 0.f : __expf(s - m);
                Sr[c] = e;
                sum += e;
            }
#pragma unroll
            for (int o = 16; o; o >>= 1) sum += __shfl_xor_sync(0xffffffffu, sum, o);
            float inv = 1.f / sum;
            float* dst = attnBase + (size_t)r * LL;
            for (int c = lane; c < 1024; c += 32) {
                float p = Sr[c] * inv;
                Sr[c] = p;
                dst[c] = p;
            }
        }
    }

    // ---- O = P @ V  (128 active threads: 4 qi x 4 d each) ----
    const int pqi0 = (tid >> 4) * 4;     // valid when tid < 128
    const int pd0  = (tid & 15) * 4;
    float4 o[4];
#pragma unroll
    for (int i = 0; i < 4; i++) o[i] = make_float4(0.f, 0.f, 0.f, 0.f);

    for (int kt = 0; kt < 16; kt++) {
        __syncthreads();
        for (int i = tid; i < 64 * 16; i += 256) {
            int r = i >> 4, s = i & 15;
            float4 v = *(const float4*)(vhp + (size_t)(kt * 64 + r) * DD + s * 4);
            *(float4*)&KV[r * 68 + s * 4] = v;
        }
        __syncthreads();
        if (tid < 128) {
#pragma unroll 4
            for (int kr = 0; kr < 64; kr++) {
                float4 v = *(const float4*)&KV[kr * 68 + pd0];
#pragma unroll
                for (int i = 0; i < 4; i++) {
                    float p = S[(pqi0 + i) * 1024 + kt * 64 + kr];
                    o[i].x += p * v.x; o[i].y += p * v.y;
                    o[i].z += p * v.z; o[i].w += p * v.w;
                }
            }
        }
    }
    if (tid < 128) {
#pragma unroll
        for (int i = 0; i < 4; i++) {
            size_t idx = ((size_t)b * LL + q0 + pqi0 + i) * DD + h * DK + pd0;
            *(float4*)&ctx[idx] = o[i];
        }
    }
}

// ---------------------------------------------------------------------------
// LayerNorm(proj + residual) * g + b   -> out
// one block per row, 256 threads x 4 elements
// ---------------------------------------------------------------------------
__global__ __launch_bounds__(256) void ln_kernel(
    const float* __restrict__ proj, const float* __restrict__ resid,
    const float* __restrict__ gam, const float* __restrict__ bet,
    float* __restrict__ out)
{
    __shared__ float red[8];
    const int row = blockIdx.x;
    const int tid = threadIdx.x;
    const int c0 = tid * 4;
    const int lane = tid & 31, wid = tid >> 5;

    float4 pv = *(const float4*)(proj + (size_t)row * DD + c0);
    float4 rv = *(const float4*)(resid + (size_t)row * DD + c0);
    float x0 = pv.x + rv.x, x1 = pv.y + rv.y, x2 = pv.z + rv.z, x3 = pv.w + rv.w;

    // mean
    float s = x0 + x1 + x2 + x3;
#pragma unroll
    for (int o = 16; o; o >>= 1) s += __shfl_xor_sync(0xffffffffu, s, o);
    if (lane == 0) red[wid] = s;
    __syncthreads();
    float tot = (lane < 8) ? red[lane] : 0.f;
#pragma unroll
    for (int o = 4; o; o >>= 1) tot += __shfl_xor_sync(0xffffffffu, tot, o);
    tot = __shfl_sync(0xffffffffu, tot, 0);
    float mean = tot * (1.f / 1024.f);

    // var
    float d0 = x0 - mean, d1 = x1 - mean, d2 = x2 - mean, d3 = x3 - mean;
    float sq = d0 * d0 + d1 * d1 + d2 * d2 + d3 * d3;
#pragma unroll
    for (int o = 16; o; o >>= 1) sq += __shfl_xor_sync(0xffffffffu, sq, o);
    __syncthreads();
    if (lane == 0) red[wid] = sq;
    __syncthreads();
    float tot2 = (lane < 8) ? red[lane] : 0.f;
#pragma unroll
    for (int o = 4; o; o >>= 1) tot2 += __shfl_xor_sync(0xffffffffu, tot2, o);
    tot2 = __shfl_sync(0xffffffffu, tot2, 0);
    float k = rsqrtf(tot2 * (1.f / 1024.f) + 1e-5f);

    float4 gv = *(const float4*)(gam + c0);
    float4 bv = *(const float4*)(bet + c0);
    float4 ov;
    ov.x = d0 * k * gv.x + bv.x;
    ov.y = d1 * k * gv.y + bv.y;
    ov.z = d2 * k * gv.z + bv.z;
    ov.w = d3 * k * gv.w + bv.w;
    *(float4*)&out[(size_t)row * DD + c0] = ov;
}

// ---------------------------------------------------------------------------
extern "C" void kernel_launch(void* const* d_in, const int* in_sizes, int n_in,
                              void* d_out, int out_size)
{
    const float* q    = (const float*)d_in[0];
    const float* k    = (const float*)d_in[1];
    const float* v    = (const float*)d_in[2];
    const int*   mask = (const int*)  d_in[3];
    const float* npm  = (const float*)d_in[4];
    const float* Wq   = (const float*)d_in[5];
    const float* bq   = (const float*)d_in[6];
    const float* Wk   = (const float*)d_in[7];
    const float* bk   = (const float*)d_in[8];
    const float* Wv   = (const float*)d_in[9];
    const float* bv   = (const float*)d_in[10];
    const float* Wf   = (const float*)d_in[11];
    const float* bf   = (const float*)d_in[12];
    const float* ln_g = (const float*)d_in[13];
    const float* ln_b = (const float*)d_in[14];

    float* out  = (float*)d_out;                       // (B,L,D)
    float* attn = out + (size_t)BB * LL * DD;          // (B,H,L,L)

    float *qh, *kh, *vh, *ctx;
    cudaGetSymbolAddress((void**)&qh,  g_qh);
    cudaGetSymbolAddress((void**)&kh,  g_kh);
    cudaGetSymbolAddress((void**)&vh,  g_vh);
    cudaGetSymbolAddress((void**)&ctx, g_ctx);

    dim3 gG(DD / 128, ROWS_TOT / 128);   // (8, 64)

    // QKV projections (scale 1/sqrt(DK) folded into qh)
    sgemm_bias<<<gG, 256>>>(q, Wq, bq, npm, 0.125f, qh, ROWS_TOT, DD, DD);
    sgemm_bias<<<gG, 256>>>(k, Wk, bk, npm, 1.0f,  kh, ROWS_TOT, DD, DD);
    sgemm_bias<<<gG, 256>>>(v, Wv, bv, npm, 1.0f,  vh, ROWS_TOT, DD, DD);

    cudaFuncSetAttribute(attn_kernel, cudaFuncAttributeMaxDynamicSharedMemorySize, ATT_SMEM);
    attn_kernel<<<dim3(BB * HH, LL / 32), 256, ATT_SMEM>>>(qh, kh, vh, mask, attn, ctx);

    // Output projection into qh scratch (qh dead now), then LN + residual
    sgemm_bias<<<gG, 256>>>(ctx, Wf, bf, npm, 1.0f, qh, ROWS_TOT, DD, DD);
    ln_kernel<<<ROWS_TOT, 256>>>(qh, q, ln_g, ln_b, out);
}

// round 2
// speedup vs baseline: 1.2270x; 1.2270x over previous
#include <cuda_runtime.h>
#include <math.h>

// Problem constants
#define BB 8
#define LL 1024
#define DD 1024
#define HH 16
#define DK 64
#define ROWS_TOT (BB*LL)          // 8192

// Scratch (device globals; no allocation allowed)
__device__ float g_qh[(size_t)ROWS_TOT * DD];   // (b,l,h,d)
__device__ float g_kh[(size_t)ROWS_TOT * DD];
__device__ float g_vh[(size_t)ROWS_TOT * DD];
__device__ float g_ctx[(size_t)ROWS_TOT * DD];  // (b,q,h,d)

// ---------------------------------------------------------------------------
// tf32 helpers
// ---------------------------------------------------------------------------
__device__ __forceinline__ unsigned f2tf(float x) {
    unsigned r;
    asm("cvt.rna.tf32.f32 %0, %1;" : "=r"(r) : "f"(x));
    return r;
}
__device__ __forceinline__ void split_tf32(float x, float& hi, float& lo) {
    hi = __uint_as_float(f2tf(x));
    lo = __uint_as_float(f2tf(x - hi));
}
__device__ __forceinline__ void mma_tf32(float c[4], const unsigned a[4], const unsigned b[2]) {
    asm volatile(
        "mma.sync.aligned.m16n8k8.row.col.f32.tf32.tf32.f32 "
        "{%0,%1,%2,%3},{%4,%5,%6,%7},{%8,%9},{%0,%1,%2,%3};"
        : "+f"(c[0]), "+f"(c[1]), "+f"(c[2]), "+f"(c[3])
        : "r"(a[0]), "r"(a[1]), "r"(a[2]), "r"(a[3]), "r"(b[0]), "r"(b[1]));
}
#define FBITS(x) __float_as_uint(x)

// ---------------------------------------------------------------------------
// C[M,N] = (A[M,K] @ W[N,K]^T + bias) * npm[row] * scale   via 3xTF32 mma
// 128x128 tile, BK=32, 256 threads (8 warps: 2m x 4n, warp tile 64x32)
// ---------------------------------------------------------------------------
#define GEMM_SMEM (4 * 128 * 36 * 4)

__global__ __launch_bounds__(256) void gemm_tf32(
    const float* __restrict__ A, const float* __restrict__ W,
    const float* __restrict__ bias, const float* __restrict__ npm,
    float scale, float* __restrict__ C, int M, int N, int K)
{
    extern __shared__ float sm[];
    float* Ah = sm;                  // [128][36]
    float* Al = Ah + 128 * 36;
    float* Bh = Al + 128 * 36;
    float* Bl = Bh + 128 * 36;

    const int tid = threadIdx.x;
    const int bm = blockIdx.y * 128;
    const int bn = blockIdx.x * 128;
    const int wid = tid >> 5, lane = tid & 31;
    const int wm = (wid & 1) * 64;
    const int wn = (wid >> 1) * 32;
    const int g = lane >> 2, tg = lane & 3;

    float acc[4][4][4];
#pragma unroll
    for (int mi = 0; mi < 4; mi++)
#pragma unroll
        for (int ni = 0; ni < 4; ni++)
#pragma unroll
            for (int r = 0; r < 4; r++) acc[mi][ni][r] = 0.f;

    for (int kb = 0; kb < K; kb += 32) {
        __syncthreads();
#pragma unroll
        for (int i = 0; i < 4; i++) {
            int lin = tid + 256 * i;           // 0..1023
            int r = lin >> 3, c4 = (lin & 7) * 4;
            float4 av = *(const float4*)(A + (size_t)(bm + r) * K + kb + c4);
            float4 h, l;
            split_tf32(av.x, h.x, l.x); split_tf32(av.y, h.y, l.y);
            split_tf32(av.z, h.z, l.z); split_tf32(av.w, h.w, l.w);
            *(float4*)&Ah[r * 36 + c4] = h;
            *(float4*)&Al[r * 36 + c4] = l;
            float4 wv = *(const float4*)(W + (size_t)(bn + r) * K + kb + c4);
            split_tf32(wv.x, h.x, l.x); split_tf32(wv.y, h.y, l.y);
            split_tf32(wv.z, h.z, l.z); split_tf32(wv.w, h.w, l.w);
            *(float4*)&Bh[r * 36 + c4] = h;
            *(float4*)&Bl[r * 36 + c4] = l;
        }
        __syncthreads();
#pragma unroll
        for (int kk = 0; kk < 4; kk++) {
            const int k0 = kk * 8 + tg;
            unsigned ah[4][4], al[4][4], bh[4][2], bl[4][2];
#pragma unroll
            for (int mi = 0; mi < 4; mi++) {
                int r = wm + mi * 16 + g;
                ah[mi][0] = FBITS(Ah[r * 36 + k0]);
                ah[mi][1] = FBITS(Ah[(r + 8) * 36 + k0]);
                ah[mi][2] = FBITS(Ah[r * 36 + k0 + 4]);
                ah[mi][3] = FBITS(Ah[(r + 8) * 36 + k0 + 4]);
                al[mi][0] = FBITS(Al[r * 36 + k0]);
                al[mi][1] = FBITS(Al[(r + 8) * 36 + k0]);
                al[mi][2] = FBITS(Al[r * 36 + k0 + 4]);
                al[mi][3] = FBITS(Al[(r + 8) * 36 + k0 + 4]);
            }
#pragma unroll
            for (int ni = 0; ni < 4; ni++) {
                int c = wn + ni * 8 + g;
                bh[ni][0] = FBITS(Bh[c * 36 + k0]);
                bh[ni][1] = FBITS(Bh[c * 36 + k0 + 4]);
                bl[ni][0] = FBITS(Bl[c * 36 + k0]);
                bl[ni][1] = FBITS(Bl[c * 36 + k0 + 4]);
            }
#pragma unroll
            for (int mi = 0; mi < 4; mi++)
#pragma unroll
                for (int ni = 0; ni < 4; ni++) {
                    mma_tf32(acc[mi][ni], ah[mi], bh[ni]);
                    mma_tf32(acc[mi][ni], ah[mi], bl[ni]);
                    mma_tf32(acc[mi][ni], al[mi], bh[ni]);
                }
        }
    }

    // epilogue
#pragma unroll
    for (int mi = 0; mi < 4; mi++) {
        int r0 = bm + wm + mi * 16 + g;
        int r1 = r0 + 8;
        float nv0 = npm[r0] * scale;
        float nv1 = npm[r1] * scale;
#pragma unroll
        for (int ni = 0; ni < 4; ni++) {
            int c0 = bn + wn + ni * 8 + 2 * tg;
            float b0 = bias[c0], b1 = bias[c0 + 1];
            C[(size_t)r0 * N + c0]     = (acc[mi][ni][0] + b0) * nv0;
            C[(size_t)r0 * N + c0 + 1] = (acc[mi][ni][1] + b1) * nv0;
            C[(size_t)r1 * N + c0]     = (acc[mi][ni][2] + b0) * nv1;
            C[(size_t)r1 * N + c0 + 1] = (acc[mi][ni][3] + b1) * nv1;
        }
    }
}

// ---------------------------------------------------------------------------
// Fused attention (tensor-core): block = (b,h) x 32 q-rows, 256 threads
// S = QK^T via 3xTF32 mma -> mask -> softmax (write attn) -> P@V via tf32 mma
// smem: S[32][1028] fp32 | Qh/Ql[32][68] | Kh/Kl[128][68]
// ---------------------------------------------------------------------------
#define SSTR 1028
#define ATT_SMEM ((32*SSTR + 2*32*68 + 2*128*68) * 4)

__global__ __launch_bounds__(256) void attn_kernel(
    const float* __restrict__ qh, const float* __restrict__ kh,
    const float* __restrict__ vh, const int* __restrict__ mask,
    float* __restrict__ attn, float* __restrict__ ctx)
{
    extern __shared__ float sm[];
    float* S  = sm;                          // [32][SSTR]
    float* Qh = S + 32 * SSTR;               // [32][68]
    float* Ql = Qh + 32 * 68;
    float* Kh = Ql + 32 * 68;                // [128][68]
    float* Kl = Kh + 128 * 68;

    const int tid = threadIdx.x;
    const int wid = tid >> 5, lane = tid & 31;
    const int g = lane >> 2, tg = lane & 3;
    const int bh = blockIdx.x;               // b*16 + h
    const int b = bh >> 4, h = bh & 15;
    const int q0 = blockIdx.y * 32;

    const float* qhp = qh + (size_t)b * LL * DD + h * DK;
    const float* khp = kh + (size_t)b * LL * DD + h * DK;
    const float* vhp = vh + (size_t)b * LL * DD + h * DK;

    // ---- load + split Q (32 x 64) ----
    for (int i = tid; i < 32 * 16; i += 256) {
        int r = i >> 4, c4 = (i & 15) * 4;
        float4 v = *(const float4*)(qhp + (size_t)(q0 + r) * DD + c4);
        float4 hh, ll;
        split_tf32(v.x, hh.x, ll.x); split_tf32(v.y, hh.y, ll.y);
        split_tf32(v.z, hh.z, ll.z); split_tf32(v.w, hh.w, ll.w);
        *(float4*)&Qh[r * 68 + c4] = hh;
        *(float4*)&Ql[r * 68 + c4] = ll;
    }

    // ---- S = Q @ K^T over 8 chunks of 128 k-rows ----
    for (int kc = 0; kc < 8; kc++) {
        __syncthreads();
        for (int i = tid; i < 128 * 16; i += 256) {
            int r = i >> 4, c4 = (i & 15) * 4;
            float4 v = *(const float4*)(khp + (size_t)(kc * 128 + r) * DD + c4);
            float4 hh, ll;
            split_tf32(v.x, hh.x, ll.x); split_tf32(v.y, hh.y, ll.y);
            split_tf32(v.z, hh.z, ll.z); split_tf32(v.w, hh.w, ll.w);
            *(float4*)&Kh[r * 68 + c4] = hh;
            *(float4*)&Kl[r * 68 + c4] = ll;
        }
        __syncthreads();

        float sacc[2][2][4];
#pragma unroll
        for (int mi = 0; mi < 2; mi++)
#pragma unroll
            for (int ni = 0; ni < 2; ni++)
#pragma unroll
                for (int r = 0; r < 4; r++) sacc[mi][ni][r] = 0.f;

#pragma unroll
        for (int kk = 0; kk < 8; kk++) {
            const int k0 = kk * 8 + tg;
            unsigned ah[2][4], al[2][4], bhf[2][2], blf[2][2];
#pragma unroll
            for (int mi = 0; mi < 2; mi++) {
                int r = mi * 16 + g;
                ah[mi][0] = FBITS(Qh[r * 68 + k0]);
                ah[mi][1] = FBITS(Qh[(r + 8) * 68 + k0]);
                ah[mi][2] = FBITS(Qh[r * 68 + k0 + 4]);
                ah[mi][3] = FBITS(Qh[(r + 8) * 68 + k0 + 4]);
                al[mi][0] = FBITS(Ql[r * 68 + k0]);
                al[mi][1] = FBITS(Ql[(r + 8) * 68 + k0]);
                al[mi][2] = FBITS(Ql[r * 68 + k0 + 4]);
                al[mi][3] = FBITS(Ql[(r + 8) * 68 + k0 + 4]);
            }
#pragma unroll
            for (int ni = 0; ni < 2; ni++) {
                int c = wid * 16 + ni * 8 + g;
                bhf[ni][0] = FBITS(Kh[c * 68 + k0]);
                bhf[ni][1] = FBITS(Kh[c * 68 + k0 + 4]);
                blf[ni][0] = FBITS(Kl[c * 68 + k0]);
                blf[ni][1] = FBITS(Kl[c * 68 + k0 + 4]);
            }
#pragma unroll
            for (int mi = 0; mi < 2; mi++)
#pragma unroll
                for (int ni = 0; ni < 2; ni++) {
                    mma_tf32(sacc[mi][ni], ah[mi], bhf[ni]);
                    mma_tf32(sacc[mi][ni], ah[mi], blf[ni]);
                    mma_tf32(sacc[mi][ni], al[mi], bhf[ni]);
                }
        }
        // write scores
#pragma unroll
        for (int mi = 0; mi < 2; mi++) {
            int r0 = mi * 16 + g;
#pragma unroll
            for (int ni = 0; ni < 2; ni++) {
                int c = kc * 128 + wid * 16 + ni * 8 + 2 * tg;
                S[r0 * SSTR + c]       = sacc[mi][ni][0];
                S[r0 * SSTR + c + 1]   = sacc[mi][ni][1];
                S[(r0 + 8) * SSTR + c]     = sacc[mi][ni][2];
                S[(r0 + 8) * SSTR + c + 1] = sacc[mi][ni][3];
            }
        }
    }
    __syncthreads();

    // ---- mask ----
    for (int i = tid; i < 32 * 256; i += 256) {
        int r = i >> 8, c4 = (i & 255) * 4;
        int4 m4 = *(const int4*)(mask + ((size_t)b * LL + q0 + r) * LL + c4);
        float* sp = S + r * SSTR + c4;
        float4 sv = *(float4*)sp;
        if (m4.x) sv.x = -1e30f;
        if (m4.y) sv.y = -1e30f;
        if (m4.z) sv.z = -1e30f;
        if (m4.w) sv.w = -1e30f;
        *(float4*)sp = sv;
    }
    __syncthreads();

    // ---- softmax per row (warp handles 4 rows) + write attn ----
    {
        float* attnBase = attn + ((size_t)bh * LL + q0) * LL;
#pragma unroll
        for (int rr = 0; rr < 4; rr++) {
            int r = wid * 4 + rr;
            float* Sr = S + r * SSTR;
            float m = -1e30f;
            for (int c = lane; c < 1024; c += 32) m = fmaxf(m, Sr[c]);
#pragma unroll
            for (int o = 16; o; o >>= 1) m = fmaxf(m, __shfl_xor_sync(0xffffffffu, m, o));
            float sum = 0.f;
            for (int c = lane; c < 1024; c += 32) {
                float s = Sr[c];
                float e = (s <= -9e29f) ? 0.f : __expf(s - m);
                Sr[c] = e;
                sum += e;
            }
#pragma unroll
            for (int o = 16; o; o >>= 1) sum += __shfl_xor_sync(0xffffffffu, sum, o);
            float inv = 1.f / sum;
            float* dst = attnBase + (size_t)r * LL;
            for (int c = lane; c < 1024; c += 32) {
                float p = Sr[c] * inv;
                Sr[c] = p;
                dst[c] = p;
            }
        }
    }

    // ---- ctx = P @ V : warp owns 8 d-cols; accumulate over 8 chunks ----
    float pacc[2][4];
#pragma unroll
    for (int mi = 0; mi < 2; mi++)
#pragma unroll
        for (int r = 0; r < 4; r++) pacc[mi][r] = 0.f;

    for (int vc = 0; vc < 8; vc++) {
        __syncthreads();
        for (int i = tid; i < 128 * 16; i += 256) {
            int r = i >> 4, c4 = (i & 15) * 4;
            float4 v = *(const float4*)(vhp + (size_t)(vc * 128 + r) * DD + c4);
            float4 hh;
            hh.x = __uint_as_float(f2tf(v.x));
            hh.y = __uint_as_float(f2tf(v.y));
            hh.z = __uint_as_float(f2tf(v.z));
            hh.w = __uint_as_float(f2tf(v.w));
            *(float4*)&Kh[r * 68 + c4] = hh;
        }
        __syncthreads();

#pragma unroll
        for (int kk = 0; kk < 16; kk++) {
            unsigned af[2][4], bf[2];
#pragma unroll
            for (int mi = 0; mi < 2; mi++) {
                int r = mi * 16 + g;
                int c = vc * 128 + kk * 8 + tg;
                af[mi][0] = f2tf(S[r * SSTR + c]);
                af[mi][1] = f2tf(S[(r + 8) * SSTR + c]);
                af[mi][2] = f2tf(S[r * SSTR + c + 4]);
                af[mi][3] = f2tf(S[(r + 8) * SSTR + c + 4]);
            }
            int vcol = wid * 8 + g;
            bf[0] = FBITS(Kh[(kk * 8 + tg) * 68 + vcol]);
            bf[1] = FBITS(Kh[(kk * 8 + tg + 4) * 68 + vcol]);
            mma_tf32(pacc[0], af[0], bf);
            mma_tf32(pacc[1], af[1], bf);
        }
    }
    // write ctx
#pragma unroll
    for (int mi = 0; mi < 2; mi++) {
        int r0 = q0 + mi * 16 + g;
        int c = h * DK + wid * 8 + 2 * tg;
        ctx[((size_t)b * LL + r0) * DD + c]     = pacc[mi][0];
        ctx[((size_t)b * LL + r0) * DD + c + 1] = pacc[mi][1];
        ctx[((size_t)b * LL + r0 + 8) * DD + c]     = pacc[mi][2];
        ctx[((size_t)b * LL + r0 + 8) * DD + c + 1] = pacc[mi][3];
    }
}

// ---------------------------------------------------------------------------
// LayerNorm(proj + residual) * g + b   -> out
// ---------------------------------------------------------------------------
__global__ __launch_bounds__(256) void ln_kernel(
    const float* __restrict__ proj, const float* __restrict__ resid,
    const float* __restrict__ gam, const float* __restrict__ bet,
    float* __restrict__ out)
{
    __shared__ float red[8];
    const int row = blockIdx.x;
    const int tid = threadIdx.x;
    const int c0 = tid * 4;
    const int lane = tid & 31, wid = tid >> 5;

    float4 pv = *(const float4*)(proj + (size_t)row * DD + c0);
    float4 rv = *(const float4*)(resid + (size_t)row * DD + c0);
    float x0 = pv.x + rv.x, x1 = pv.y + rv.y, x2 = pv.z + rv.z, x3 = pv.w + rv.w;

    float s = x0 + x1 + x2 + x3;
#pragma unroll
    for (int o = 16; o; o >>= 1) s += __shfl_xor_sync(0xffffffffu, s, o);
    if (lane == 0) red[wid] = s;
    __syncthreads();
    float tot = (lane < 8) ? red[lane] : 0.f;
#pragma unroll
    for (int o = 4; o; o >>= 1) tot += __shfl_xor_sync(0xffffffffu, tot, o);
    tot = __shfl_sync(0xffffffffu, tot, 0);
    float mean = tot * (1.f / 1024.f);

    float d0 = x0 - mean, d1 = x1 - mean, d2 = x2 - mean, d3 = x3 - mean;
    float sq = d0 * d0 + d1 * d1 + d2 * d2 + d3 * d3;
#pragma unroll
    for (int o = 16; o; o >>= 1) sq += __shfl_xor_sync(0xffffffffu, sq, o);
    __syncthreads();
    if (lane == 0) red[wid] = sq;
    __syncthreads();
    float tot2 = (lane < 8) ? red[lane] : 0.f;
#pragma unroll
    for (int o = 4; o; o >>= 1) tot2 += __shfl_xor_sync(0xffffffffu, tot2, o);
    tot2 = __shfl_sync(0xffffffffu, tot2, 0);
    float k = rsqrtf(tot2 * (1.f / 1024.f) + 1e-5f);

    float4 gv = *(const float4*)(gam + c0);
    float4 bv = *(const float4*)(bet + c0);
    float4 ov;
    ov.x = d0 * k * gv.x + bv.x;
    ov.y = d1 * k * gv.y + bv.y;
    ov.z = d2 * k * gv.z + bv.z;
    ov.w = d3 * k * gv.w + bv.w;
    *(float4*)&out[(size_t)row * DD + c0] = ov;
}

// ---------------------------------------------------------------------------
extern "C" void kernel_launch(void* const* d_in, const int* in_sizes, int n_in,
                              void* d_out, int out_size)
{
    const float* q    = (const float*)d_in[0];
    const float* k    = (const float*)d_in[1];
    const float* v    = (const float*)d_in[2];
    const int*   mask = (const int*)  d_in[3];
    const float* npm  = (const float*)d_in[4];
    const float* Wq   = (const float*)d_in[5];
    const float* bq   = (const float*)d_in[6];
    const float* Wk   = (const float*)d_in[7];
    const float* bk   = (const float*)d_in[8];
    const float* Wv   = (const float*)d_in[9];
    const float* bv   = (const float*)d_in[10];
    const float* Wf   = (const float*)d_in[11];
    const float* bf   = (const float*)d_in[12];
    const float* ln_g = (const float*)d_in[13];
    const float* ln_b = (const float*)d_in[14];

    float* out  = (float*)d_out;                       // (B,L,D)
    float* attn = out + (size_t)BB * LL * DD;          // (B,H,L,L)

    float *qh, *kh, *vh, *ctx;
    cudaGetSymbolAddress((void**)&qh,  g_qh);
    cudaGetSymbolAddress((void**)&kh,  g_kh);
    cudaGetSymbolAddress((void**)&vh,  g_vh);
    cudaGetSymbolAddress((void**)&ctx, g_ctx);

    cudaFuncSetAttribute(gemm_tf32, cudaFuncAttributeMaxDynamicSharedMemorySize, GEMM_SMEM);
    cudaFuncSetAttribute(attn_kernel, cudaFuncAttributeMaxDynamicSharedMemorySize, ATT_SMEM);

    dim3 gG(DD / 128, ROWS_TOT / 128);   // (8, 64)

    gemm_tf32<<<gG, 256, GEMM_SMEM>>>(q, Wq, bq, npm, 0.125f, qh, ROWS_TOT, DD, DD);
    gemm_tf32<<<gG, 256, GEMM_SMEM>>>(k, Wk, bk, npm, 1.0f,  kh, ROWS_TOT, DD, DD);
    gemm_tf32<<<gG, 256, GEMM_SMEM>>>(v, Wv, bv, npm, 1.0f,  vh, ROWS_TOT, DD, DD);

    attn_kernel<<<dim3(BB * HH, LL / 32), 256, ATT_SMEM>>>(qh, kh, vh, mask, attn, ctx);

    gemm_tf32<<<gG, 256, GEMM_SMEM>>>(ctx, Wf, bf, npm, 1.0f, qh, ROWS_TOT, DD, DD);
    ln_kernel<<<ROWS_TOT, 256>>>(qh, q, ln_g, ln_b, out);
}

// round 4
// speedup vs baseline: 2.2073x; 1.7989x over previous
#include <cuda_runtime.h>
#include <cuda_bf16.h>
#include <math.h>
#include <cstdint>

#define BB 8
#define LL 1024
#define DD 1024
#define HH 16
#define DK 64
#define ROWS_TOT (BB*LL)          // 8192

// Scratch (device globals)
__device__ __nv_bfloat16 g_qhH[(size_t)ROWS_TOT * DD];
__device__ __nv_bfloat16 g_qhL[(size_t)ROWS_TOT * DD];
__device__ __nv_bfloat16 g_khH[(size_t)ROWS_TOT * DD];
__device__ __nv_bfloat16 g_khL[(size_t)ROWS_TOT * DD];
__device__ float g_vh [(size_t)ROWS_TOT * DD];
__device__ float g_ctx[(size_t)ROWS_TOT * DD];
__device__ float g_proj[(size_t)ROWS_TOT * DD];
__device__ __nv_bfloat16 g_asH[(size_t)ROWS_TOT * DD];
__device__ __nv_bfloat16 g_asL[(size_t)ROWS_TOT * DD];
__device__ __nv_bfloat16 g_wsH[(size_t)DD * DD];
__device__ __nv_bfloat16 g_wsL[(size_t)DD * DD];

// ---------------------------------------------------------------------------
// helpers
// ---------------------------------------------------------------------------
__device__ __forceinline__ uint32_t smem_u32(const void* p) {
    uint32_t a;
    asm("{ .reg .u64 t; cvta.to.shared.u64 t, %1; cvt.u32.u64 %0, t; }" : "=r"(a) : "l"(p));
    return a;
}
__device__ __forceinline__ void cp16(uint32_t dst, const void* src) {
    asm volatile("cp.async.cg.shared.global [%0], [%1], 16;" :: "r"(dst), "l"(src));
}
#define CP_COMMIT asm volatile("cp.async.commit_group;" ::: "memory")
#define CP_WAIT1  asm volatile("cp.async.wait_group 1;" ::: "memory")
#define CP_WAIT0  asm volatile("cp.async.wait_group 0;" ::: "memory")

__device__ __forceinline__ void mma_bf16(float* c, const uint32_t* a, const uint32_t* b) {
    asm volatile(
        "mma.sync.aligned.m16n8k16.row.col.f32.bf16.bf16.f32 "
        "{%0,%1,%2,%3},{%4,%5,%6,%7},{%8,%9},{%0,%1,%2,%3};"
        : "+f"(c[0]), "+f"(c[1]), "+f"(c[2]), "+f"(c[3])
        : "r"(a[0]), "r"(a[1]), "r"(a[2]), "r"(a[3]), "r"(b[0]), "r"(b[1]));
}
__device__ __forceinline__ unsigned f2tf(float x) {
    unsigned r;
    asm("cvt.rna.tf32.f32 %0, %1;" : "=r"(r) : "f"(x));
    return r;
}
__device__ __forceinline__ void mma_tf32(float c[4], const unsigned a[4], const unsigned b[2]) {
    asm volatile(
        "mma.sync.aligned.m16n8k8.row.col.f32.tf32.tf32.f32 "
        "{%0,%1,%2,%3},{%4,%5,%6,%7},{%8,%9},{%0,%1,%2,%3};"
        : "+f"(c[0]), "+f"(c[1]), "+f"(c[2]), "+f"(c[3])
        : "r"(a[0]), "r"(a[1]), "r"(a[2]), "r"(a[3]), "r"(b[0]), "r"(b[1]));
}

// ---------------------------------------------------------------------------
// bf16 hi/lo split: x -> h = bf16(x), l = bf16(x - h)
// ---------------------------------------------------------------------------
__global__ __launch_bounds__(256) void split_bf16(
    const float* __restrict__ x, __nv_bfloat16* __restrict__ hi,
    __nv_bfloat16* __restrict__ lo, int n4)
{
    int i = blockIdx.x * blockDim.x + threadIdx.x;
    if (i >= n4) return;
    float4 v = ((const float4*)x)[i];
    __nv_bfloat16 h0 = __float2bfloat16(v.x);
    __nv_bfloat16 h1 = __float2bfloat16(v.y);
    __nv_bfloat16 h2 = __float2bfloat16(v.z);
    __nv_bfloat16 h3 = __float2bfloat16(v.w);
    __nv_bfloat16 l0 = __float2bfloat16(v.x - __bfloat162float(h0));
    __nv_bfloat16 l1 = __float2bfloat16(v.y - __bfloat162float(h1));
    __nv_bfloat16 l2 = __float2bfloat16(v.z - __bfloat162float(h2));
    __nv_bfloat16 l3 = __float2bfloat16(v.w - __bfloat162float(h3));
    ((__nv_bfloat162*)hi)[i * 2]     = __nv_bfloat162(h0, h1);
    ((__nv_bfloat162*)hi)[i * 2 + 1] = __nv_bfloat162(h2, h3);
    ((__nv_bfloat162*)lo)[i * 2]     = __nv_bfloat162(l0, l1);
    ((__nv_bfloat162*)lo)[i * 2 + 1] = __nv_bfloat162(l2, l3);
}

// ===========================================================================
// bf16-split GEMM: C[M,N] = (A @ W^T + bias) * npm[row] * scale
// 128x128 tile, BK=32, 512 threads (16 warps: 2m x 8n, warp tile 64x16)
// cp.async double-buffered. Output: fp32 OR bf16 hi/lo planes.
// smem: 2 buffers x 4 planes x [128][40] bf16 = 81920 B
// ===========================================================================
#define PL_E 5120                     // plane elems (128*40)
#define PL_B (PL_E*2)                 // 10240 B
#define BUF_B (4*PL_B)                // 40960 B
#define GEMM_SMEM (2*BUF_B)           // 81920 B

__global__ __launch_bounds__(512) void gemm_bf16(
    const __nv_bfloat16* __restrict__ Ah, const __nv_bfloat16* __restrict__ Al,
    const __nv_bfloat16* __restrict__ Bh, const __nv_bfloat16* __restrict__ Bl,
    const float* __restrict__ bias, const float* __restrict__ npm, float scale,
    float* __restrict__ outF, __nv_bfloat16* __restrict__ outH,
    __nv_bfloat16* __restrict__ outL)
{
    extern __shared__ char sm[];
    const uint32_t smb = smem_u32(sm);
    const int tid = threadIdx.x, wid = tid >> 5, lane = tid & 31;
    const int g = lane >> 2, tg = lane & 3;
    const int bm = blockIdx.y * 128, bn = blockIdx.x * 128;
    const int wm = (wid & 1) * 64, wn = (wid >> 1) * 16;

    const __nv_bfloat16* srcs[4] = { Ah + (size_t)bm * DD, Al + (size_t)bm * DD,
                                     Bh + (size_t)bn * DD, Bl + (size_t)bn * DD };
    const int frow = tid >> 2, fc = tid & 3;   // fill: row 0..127, chunk 0..3

    float acc[4][2][4];
#pragma unroll
    for (int mi = 0; mi < 4; mi++)
#pragma unroll
        for (int ni = 0; ni < 2; ni++)
#pragma unroll
            for (int r = 0; r < 4; r++) acc[mi][ni][r] = 0.f;

    // prefill kt=0 into buf0
#pragma unroll
    for (int i = 0; i < 4; i++)
        cp16(smb + i * PL_B + frow * 80 + fc * 16,
             srcs[i] + (size_t)frow * DD + fc * 8);
    CP_COMMIT;

    for (int kt = 0; kt < 32; kt++) {
        if (kt < 31) {
#pragma unroll
            for (int i = 0; i < 4; i++)
                cp16(smb + ((kt + 1) & 1) * BUF_B + i * PL_B + frow * 80 + fc * 16,
                     srcs[i] + (size_t)frow * DD + (kt + 1) * 32 + fc * 8);
            CP_COMMIT;
            CP_WAIT1;
        } else {
            CP_WAIT0;
        }
        __syncthreads();

        const __nv_bfloat16* buf = (const __nv_bfloat16*)(sm + (kt & 1) * BUF_B);
#pragma unroll
        for (int ks = 0; ks < 2; ks++) {
            uint32_t a_h[4][4], a_l[4][4], b_h[2][2], b_l[2][2];
#pragma unroll
            for (int mi = 0; mi < 4; mi++) {
                const __nv_bfloat16* p = buf + (wm + mi * 16 + g) * 40 + ks * 16 + 2 * tg;
                a_h[mi][0] = *(const uint32_t*)(p);
                a_h[mi][1] = *(const uint32_t*)(p + 8 * 40);
                a_h[mi][2] = *(const uint32_t*)(p + 8);
                a_h[mi][3] = *(const uint32_t*)(p + 8 * 40 + 8);
                a_l[mi][0] = *(const uint32_t*)(p + PL_E);
                a_l[mi][1] = *(const uint32_t*)(p + PL_E + 8 * 40);
                a_l[mi][2] = *(const uint32_t*)(p + PL_E + 8);
                a_l[mi][3] = *(const uint32_t*)(p + PL_E + 8 * 40 + 8);
            }
#pragma unroll
            for (int ni = 0; ni < 2; ni++) {
                const __nv_bfloat16* p = buf + 2 * PL_E + (wn + ni * 8 + g) * 40 + ks * 16 + 2 * tg;
                b_h[ni][0] = *(const uint32_t*)(p);
                b_h[ni][1] = *(const uint32_t*)(p + 8);
                b_l[ni][0] = *(const uint32_t*)(p + PL_E);
                b_l[ni][1] = *(const uint32_t*)(p + PL_E + 8);
            }
#pragma unroll
            for (int mi = 0; mi < 4; mi++)
#pragma unroll
                for (int ni = 0; ni < 2; ni++) {
                    mma_bf16(acc[mi][ni], a_h[mi], b_h[ni]);
                    mma_bf16(acc[mi][ni], a_h[mi], b_l[ni]);
                    mma_bf16(acc[mi][ni], a_l[mi], b_h[ni]);
                }
        }
        __syncthreads();
    }

    // epilogue
#pragma unroll
    for (int mi = 0; mi < 4; mi++) {
        int r0 = bm + wm + mi * 16 + g, r1 = r0 + 8;
        float nv0 = npm[r0] * scale, nv1 = npm[r1] * scale;
#pragma unroll
        for (int ni = 0; ni < 2; ni++) {
            int c0 = bn + wn + ni * 8 + 2 * tg;
            float b0 = bias[c0], b1 = bias[c0 + 1];
            float v00 = (acc[mi][ni][0] + b0) * nv0, v01 = (acc[mi][ni][1] + b1) * nv0;
            float v10 = (acc[mi][ni][2] + b0) * nv1, v11 = (acc[mi][ni][3] + b1) * nv1;
            if (outF) {
                *(float2*)&outF[(size_t)r0 * DD + c0] = make_float2(v00, v01);
                *(float2*)&outF[(size_t)r1 * DD + c0] = make_float2(v10, v11);
            } else {
                __nv_bfloat16 h00 = __float2bfloat16(v00), h01 = __float2bfloat16(v01);
                __nv_bfloat16 h10 = __float2bfloat16(v10), h11 = __float2bfloat16(v11);
                *(__nv_bfloat162*)&outH[(size_t)r0 * DD + c0] = __nv_bfloat162(h00, h01);
                *(__nv_bfloat162*)&outH[(size_t)r1 * DD + c0] = __nv_bfloat162(h10, h11);
                *(__nv_bfloat162*)&outL[(size_t)r0 * DD + c0] = __nv_bfloat162(
                    __float2bfloat16(v00 - __bfloat162float(h00)),
                    __float2bfloat16(v01 - __bfloat162float(h01)));
                *(__nv_bfloat162*)&outL[(size_t)r1 * DD + c0] = __nv_bfloat162(
                    __float2bfloat16(v10 - __bfloat162float(h10)),
                    __float2bfloat16(v11 - __bfloat162float(h11)));
            }
        }
    }
}

// ===========================================================================
// Fused attention: block = (b,h) x 16 q-rows, 256 threads (8 warps), 2 CTA/SM
// S = QK^T bf16-split mma (Q/K pre-split planes) -> mask+softmax -> PV tf32
// smem: S[16][1028] f32 | Qh/Ql[16][72] bf16 | Kh/Kl[128][72] bf16 (V f32 reuse)
// ===========================================================================
#define SOFF 0
#define SSTR 1028
#define QOFF 65792                    // 16*1028*4
#define KOFF (QOFF + 2*2304)          // Qh,Ql each 16*72*2=2304 B
#define KPL  18432                    // 128*72*2
#define ATT_SMEM (KOFF + 2*KPL)       // 107264 B

__global__ __launch_bounds__(256) void attn_kernel(
    const __nv_bfloat16* __restrict__ qhH, const __nv_bfloat16* __restrict__ qhL,
    const __nv_bfloat16* __restrict__ khH, const __nv_bfloat16* __restrict__ khL,
    const float* __restrict__ vh, const int* __restrict__ mask,
    float* __restrict__ attn, float* __restrict__ ctx)
{
    extern __shared__ char sm[];
    const uint32_t smb = smem_u32(sm);
    float* S = (float*)(sm + SOFF);
    const __nv_bfloat16* Qh = (const __nv_bfloat16*)(sm + QOFF);
    const __nv_bfloat16* Ql = (const __nv_bfloat16*)(sm + QOFF + 2304);
    const __nv_bfloat16* Kh = (const __nv_bfloat16*)(sm + KOFF);
    const __nv_bfloat16* Kl = (const __nv_bfloat16*)(sm + KOFF + KPL);
    float* Vs = (float*)(sm + KOFF);   // PV phase reuse, stride 68

    const int tid = threadIdx.x, wid = tid >> 5, lane = tid & 31;
    const int g = lane >> 2, tg = lane & 3;
    const int bh = blockIdx.x;
    const int b = bh >> 4, h = bh & 15;
    const int q0 = blockIdx.y * 16;

    // ---- load Q planes (16 x 64 x 2) ----
    {
        int p = tid >> 7, cid = tid & 127, row = cid >> 3, c8 = cid & 7;
        const __nv_bfloat16* src = (p ? qhL : qhH) +
            ((size_t)b * LL + q0 + row) * DD + h * DK + c8 * 8;
        *(uint4*)(sm + QOFF + p * 2304 + row * 144 + c8 * 16) = *(const uint4*)src;
    }

    // ---- S = Q @ K^T over 8 chunks of 128 k-rows ----
    for (int kc = 0; kc < 8; kc++) {
        __syncthreads();   // prior mma / Q-store done before refill
#pragma unroll
        for (int i = 0; i < 8; i++) {
            int cid = tid + 256 * (i & 3);
            int row = cid >> 3, c8 = cid & 7;
            const __nv_bfloat16* src = (i < 4 ? khH : khL) +
                ((size_t)b * LL + kc * 128 + row) * DD + h * DK + c8 * 8;
            cp16(smb + KOFF + (i < 4 ? 0 : KPL) + row * 144 + c8 * 16, src);
        }
        CP_COMMIT; CP_WAIT0;
        __syncthreads();

        float sacc[2][4];
#pragma unroll
        for (int ni = 0; ni < 2; ni++)
#pragma unroll
            for (int r = 0; r < 4; r++) sacc[ni][r] = 0.f;

#pragma unroll
        for (int ks = 0; ks < 4; ks++) {
            uint32_t a_h[4], a_l[4], b_h[2][2], b_l[2][2];
            const __nv_bfloat16* qp = Qh + g * 72 + ks * 16 + 2 * tg;
            a_h[0] = *(const uint32_t*)(qp);
            a_h[1] = *(const uint32_t*)(qp + 8 * 72);
            a_h[2] = *(const uint32_t*)(qp + 8);
            a_h[3] = *(const uint32_t*)(qp + 8 * 72 + 8);
            const __nv_bfloat16* qpl = qp + 1152;   // Ql offset in elems (2304 B)
            a_l[0] = *(const uint32_t*)(qpl);
            a_l[1] = *(const uint32_t*)(qpl + 8 * 72);
            a_l[2] = *(const uint32_t*)(qpl + 8);
            a_l[3] = *(const uint32_t*)(qpl + 8 * 72 + 8);
#pragma unroll
            for (int ni = 0; ni < 2; ni++) {
                const __nv_bfloat16* kp = Kh + (wid * 16 + ni * 8 + g) * 72 + ks * 16 + 2 * tg;
                b_h[ni][0] = *(const uint32_t*)(kp);
                b_h[ni][1] = *(const uint32_t*)(kp + 8);
                b_l[ni][0] = *(const uint32_t*)(kp + KPL / 2);
                b_l[ni][1] = *(const uint32_t*)(kp + KPL / 2 + 8);
            }
#pragma unroll
            for (int ni = 0; ni < 2; ni++) {
                mma_bf16(sacc[ni], a_h, b_h[ni]);
                mma_bf16(sacc[ni], a_h, b_l[ni]);
                mma_bf16(sacc[ni], a_l, b_h[ni]);
            }
        }
#pragma unroll
        for (int ni = 0; ni < 2; ni++) {
            int c = kc * 128 + wid * 16 + ni * 8 + 2 * tg;
            *(float2*)&S[g * SSTR + c]       = make_float2(sacc[ni][0], sacc[ni][1]);
            *(float2*)&S[(g + 8) * SSTR + c] = make_float2(sacc[ni][2], sacc[ni][3]);
        }
    }
    __syncthreads();

    // ---- mask + softmax (warp handles 2 rows) + write attn ----
    {
        float* attnBase = attn + ((size_t)bh * LL + q0) * LL;
#pragma unroll
        for (int rr = 0; rr < 2; rr++) {
            int r = wid * 2 + rr;
            float* Sr = S + r * SSTR;
            const int* mr = mask + ((size_t)b * LL + q0 + r) * LL;
            float m = -1e30f;
            for (int c = lane; c < 1024; c += 32) {
                float s = Sr[c];
                if (mr[c]) s = -1e30f;
                Sr[c] = s;
                m = fmaxf(m, s);
            }
#pragma unroll
            for (int o = 16; o; o >>= 1) m = fmaxf(m, __shfl_xor_sync(0xffffffffu, m, o));
            float sum = 0.f;
            for (int c = lane; c < 1024; c += 32) {
                float s = Sr[c];
                float e = (s <= -9e29f) ? 0.f : __expf(s - m);
                Sr[c] = e;
                sum += e;
            }
#pragma unroll
            for (int o = 16; o; o >>= 1) sum += __shfl_xor_sync(0xffffffffu, sum, o);
            float inv = 1.f / sum;
            float* dst = attnBase + (size_t)r * LL;
            for (int c = lane; c < 1024; c += 32) {
                float p = Sr[c] * inv;
                Sr[c] = p;
                dst[c] = p;
            }
        }
    }

    // ---- ctx = P @ V (tf32): warp owns 8 d-cols ----
    float pacc[4] = {0.f, 0.f, 0.f, 0.f};
    for (int vc = 0; vc < 8; vc++) {
        __syncthreads();
#pragma unroll
        for (int i = 0; i < 8; i++) {
            int idx = tid + 256 * i;
            int row = idx >> 4, c4 = idx & 15;
            const float* src = vh + ((size_t)b * LL + vc * 128 + row) * DD + h * DK + c4 * 4;
            cp16(smb + KOFF + row * 272 + c4 * 16, src);
        }
        CP_COMMIT; CP_WAIT0;
        __syncthreads();

        const int vcol = wid * 8 + g;
#pragma unroll
        for (int kk = 0; kk < 16; kk++) {
            unsigned af[4], bf2[2];
            int c = vc * 128 + kk * 8 + tg;
            af[0] = f2tf(S[g * SSTR + c]);
            af[1] = f2tf(S[(g + 8) * SSTR + c]);
            af[2] = f2tf(S[g * SSTR + c + 4]);
            af[3] = f2tf(S[(g + 8) * SSTR + c + 4]);
            bf2[0] = __float_as_uint(Vs[(kk * 8 + tg) * 68 + vcol]);
            bf2[1] = __float_as_uint(Vs[(kk * 8 + tg + 4) * 68 + vcol]);
            mma_tf32(pacc, af, bf2);
        }
    }
    {
        int c = h * DK + wid * 8 + 2 * tg;
        *(float2*)&ctx[((size_t)b * LL + q0 + g) * DD + c]     = make_float2(pacc[0], pacc[1]);
        *(float2*)&ctx[((size_t)b * LL + q0 + g + 8) * DD + c] = make_float2(pacc[2], pacc[3]);
    }
}

// ---------------------------------------------------------------------------
// LayerNorm(proj + residual) * g + b
// ---------------------------------------------------------------------------
__global__ __launch_bounds__(256) void ln_kernel(
    const float* __restrict__ proj, const float* __restrict__ resid,
    const float* __restrict__ gam, const float* __restrict__ bet,
    float* __restrict__ out)
{
    __shared__ float red[8];
    const int row = blockIdx.x;
    const int tid = threadIdx.x;
    const int c0 = tid * 4;
    const int lane = tid & 31, wid = tid >> 5;

    float4 pv = *(const float4*)(proj + (size_t)row * DD + c0);
    float4 rv = *(const float4*)(resid + (size_t)row * DD + c0);
    float x0 = pv.x + rv.x, x1 = pv.y + rv.y, x2 = pv.z + rv.z, x3 = pv.w + rv.w;

    float s = x0 + x1 + x2 + x3;
#pragma unroll
    for (int o = 16; o; o >>= 1) s += __shfl_xor_sync(0xffffffffu, s, o);
    if (lane == 0) red[wid] = s;
    __syncthreads();
    float tot = (lane < 8) ? red[lane] : 0.f;
#pragma unroll
    for (int o = 4; o; o >>= 1) tot += __shfl_xor_sync(0xffffffffu, tot, o);
    tot = __shfl_sync(0xffffffffu, tot, 0);
    float mean = tot * (1.f / 1024.f);

    float d0 = x0 - mean, d1 = x1 - mean, d2 = x2 - mean, d3 = x3 - mean;
    float sq = d0 * d0 + d1 * d1 + d2 * d2 + d3 * d3;
#pragma unroll
    for (int o = 16; o; o >>= 1) sq += __shfl_xor_sync(0xffffffffu, sq, o);
    __syncthreads();
    if (lane == 0) red[wid] = sq;
    __syncthreads();
    float tot2 = (lane < 8) ? red[lane] : 0.f;
#pragma unroll
    for (int o = 4; o; o >>= 1) tot2 += __shfl_xor_sync(0xffffffffu, tot2, o);
    tot2 = __shfl_sync(0xffffffffu, tot2, 0);
    float k = rsqrtf(tot2 * (1.f / 1024.f) + 1e-5f);

    float4 gv = *(const float4*)(gam + c0);
    float4 bv = *(const float4*)(bet + c0);
    float4 ov;
    ov.x = d0 * k * gv.x + bv.x;
    ov.y = d1 * k * gv.y + bv.y;
    ov.z = d2 * k * gv.z + bv.z;
    ov.w = d3 * k * gv.w + bv.w;
    *(float4*)&out[(size_t)row * DD + c0] = ov;
}

// ---------------------------------------------------------------------------
extern "C" void kernel_launch(void* const* d_in, const int* in_sizes, int n_in,
                              void* d_out, int out_size)
{
    const float* q    = (const float*)d_in[0];
    const float* k    = (const float*)d_in[1];
    const float* v    = (const float*)d_in[2];
    const int*   mask = (const int*)  d_in[3];
    const float* npm  = (const float*)d_in[4];
    const float* Wq   = (const float*)d_in[5];
    const float* bq   = (const float*)d_in[6];
    const float* Wk   = (const float*)d_in[7];
    const float* bk   = (const float*)d_in[8];
    const float* Wv   = (const float*)d_in[9];
    const float* bv   = (const float*)d_in[10];
    const float* Wf   = (const float*)d_in[11];
    const float* bf   = (const float*)d_in[12];
    const float* ln_g = (const float*)d_in[13];
    const float* ln_b = (const float*)d_in[14];

    float* out  = (float*)d_out;                       // (B,L,D)
    float* attn = out + (size_t)BB * LL * DD;          // (B,H,L,L)

    __nv_bfloat16 *qhH, *qhL, *khH, *khL, *asH, *asL, *wsH, *wsL;
    float *vh, *ctx, *proj;
    cudaGetSymbolAddress((void**)&qhH, g_qhH);
    cudaGetSymbolAddress((void**)&qhL, g_qhL);
    cudaGetSymbolAddress((void**)&khH, g_khH);
    cudaGetSymbolAddress((void**)&khL, g_khL);
    cudaGetSymbolAddress((void**)&vh,  g_vh);
    cudaGetSymbolAddress((void**)&ctx, g_ctx);
    cudaGetSymbolAddress((void**)&proj, g_proj);
    cudaGetSymbolAddress((void**)&asH, g_asH);
    cudaGetSymbolAddress((void**)&asL, g_asL);
    cudaGetSymbolAddress((void**)&wsH, g_wsH);
    cudaGetSymbolAddress((void**)&wsL, g_wsL);

    cudaFuncSetAttribute(gemm_bf16, cudaFuncAttributeMaxDynamicSharedMemorySize, GEMM_SMEM);
    cudaFuncSetAttribute(attn_kernel, cudaFuncAttributeMaxDynamicSharedMemorySize, ATT_SMEM);

    const int nA4 = ROWS_TOT * DD / 4;
    const int nW4 = DD * DD / 4;
    dim3 gG(DD / 128, ROWS_TOT / 128);   // (8, 64)

    // Q projection -> bf16 planes (scale 1/8 folded)
    split_bf16<<<(nA4 + 255) / 256, 256>>>(q, asH, asL, nA4);
    split_bf16<<<(nW4 + 255) / 256, 256>>>(Wq, wsH, wsL, nW4);
    gemm_bf16<<<gG, 512, GEMM_SMEM>>>(asH, asL, wsH, wsL, bq, npm, 0.125f,
                                      nullptr, qhH, qhL);
    // K projection -> bf16 planes
    split_bf16<<<(nA4 + 255) / 256, 256>>>(k, asH, asL, nA4);
    split_bf16<<<(nW4 + 255) / 256, 256>>>(Wk, wsH, wsL, nW4);
    gemm_bf16<<<gG, 512, GEMM_SMEM>>>(asH, asL, wsH, wsL, bk, npm, 1.0f,
                                      nullptr, khH, khL);
    // V projection -> fp32
    split_bf16<<<(nA4 + 255) / 256, 256>>>(v, asH, asL, nA4);
    split_bf16<<<(nW4 + 255) / 256, 256>>>(Wv, wsH, wsL, nW4);
    gemm_bf16<<<gG, 512, GEMM_SMEM>>>(asH, asL, wsH, wsL, bv, npm, 1.0f,
                                      vh, nullptr, nullptr);

    attn_kernel<<<dim3(BB * HH, LL / 16), 256, ATT_SMEM>>>(
        qhH, qhL, khH, khL, vh, mask, attn, ctx);

    // Output projection -> fp32, then LN
    split_bf16<<<(nA4 + 255) / 256, 256>>>(ctx, asH, asL, nA4);
    split_bf16<<<(nW4 + 255) / 256, 256>>>(Wf, wsH, wsL, nW4);
    gemm_bf16<<<gG, 512, GEMM_SMEM>>>(asH, asL, wsH, wsL, bf, npm, 1.0f,
                                      proj, nullptr, nullptr);

    ln_kernel<<<ROWS_TOT, 256>>>(proj, q, ln_g, ln_b, out);
}